// round 11
// baseline (speedup 1.0000x reference)
#include <cuda_runtime.h>
#include <cuda_fp16.h>
#include <cstdint>

// Sliding-window attention B=2 H=12 T=4096 D=64 fp32, window [q-128, q+127].
// fp16 m16n8k16 mma.sync; ldmatrix K/V frags; P stays in registers.
// Round 11 = round 8 (best) with __launch_bounds__(256,3): cap regs at 85 so
// 3 CTAs (24 warps) fit per SM — more warps to hide the LDSM->MMA / HMMA /
// ex2 dependency chains that bound issue% at ~30.

constexpr int T_FIX = 4096;
constexpr int MQ    = 128;
constexpr int STR   = 36;     // row stride in u32 (half2) units; conflict-free

__device__ __forceinline__ uint32_t smem_u32(const void* p) {
    uint32_t a;
    asm("{ .reg .u64 t; cvta.to.shared.u64 t, %1; cvt.u32.u64 %0, t; }" : "=r"(a) : "l"(p));
    return a;
}
__device__ __forceinline__ float ex2(float x) {
    float y; asm("ex2.approx.ftz.f32 %0, %1;" : "=f"(y) : "f"(x)); return y;
}
__device__ __forceinline__ uint32_t packh2(float lo, float hi) {
    __half2 h = __floats2half2_rn(lo, hi);
    return *(uint32_t*)&h;
}
__device__ __forceinline__ void mma16(float* c, const uint32_t* a,
                                      uint32_t b0, uint32_t b1) {
    asm volatile(
        "mma.sync.aligned.m16n8k16.row.col.f32.f16.f16.f32 "
        "{%0,%1,%2,%3}, {%4,%5,%6,%7}, {%8,%9}, {%0,%1,%2,%3};"
        : "+f"(c[0]), "+f"(c[1]), "+f"(c[2]), "+f"(c[3])
        : "r"(a[0]), "r"(a[1]), "r"(a[2]), "r"(a[3]), "r"(b0), "r"(b1));
}
#define LDSM4(r0,r1,r2,r3,addr) \
    asm volatile("ldmatrix.sync.aligned.m8n8.x4.shared.b16 {%0,%1,%2,%3}, [%4];" \
        : "=r"(r0),"=r"(r1),"=r"(r2),"=r"(r3) : "r"(addr))
#define LDSM4T(r0,r1,r2,r3,addr) \
    asm volatile("ldmatrix.sync.aligned.m8n8.x4.trans.shared.b16 {%0,%1,%2,%3}, [%4];" \
        : "=r"(r0),"=r"(r1),"=r"(r2),"=r"(r3) : "r"(addr))

__global__ __launch_bounds__(256, 3)
void swa_f16_kernel(const float* __restrict__ Q, const float* __restrict__ K,
                    const float* __restrict__ V, float* __restrict__ O)
{
    __shared__ __align__(16) uint32_t sQ[128 * STR];
    __shared__ __align__(16) uint32_t sK[64 * STR];
    __shared__ __align__(16) uint32_t sV[64 * STR];

    const int tid  = threadIdx.x;
    const int lane = tid & 31;
    const int w    = tid >> 5;

    const int ntiles = T_FIX / MQ;                  // 32
    const int bh = blockIdx.x / ntiles;
    const int q0 = (blockIdx.x % ntiles) * MQ;
    const size_t base = (size_t)bh * T_FIX * 64;
    const float4* Qg = (const float4*)(Q + base);
    const float4* Kg = (const float4*)(K + base);
    const float4* Vg = (const float4*)(V + base);
    float*        Ob = O + base;

    const float SC = 1.4426950408889634f * 0.125f;  // log2(e)/sqrt(64)

    // ---- Stage Q (scaled, f16) ----
    #pragma unroll
    for (int i = 0; i < 8; i++) {
        int idx = tid + i * 256;
        int row = idx >> 4, c4 = idx & 15;
        float4 v = Qg[(size_t)(q0 + row) * 16 + c4];
        sQ[row * STR + c4 * 2]     = packh2(v.x * SC, v.y * SC);
        sQ[row * STR + c4 * 2 + 1] = packh2(v.z * SC, v.w * SC);
    }
    __syncthreads();

    // ---- Q a-fragments (m16n8k16): qa[s] covers dims 16s..16s+15 ----
    const int rA = w * 16 + (lane >> 2);
    const int cA = lane & 3;
    uint32_t qa[4][4];
    #pragma unroll
    for (int s = 0; s < 4; s++) {
        qa[s][0] = sQ[rA * STR + s * 8 + cA];
        qa[s][1] = sQ[(rA + 8) * STR + s * 8 + cA];
        qa[s][2] = sQ[rA * STR + s * 8 + 4 + cA];
        qa[s][3] = sQ[(rA + 8) * STR + s * 8 + 4 + cA];
    }

    // ---- ldmatrix per-lane base addresses (bytes) ----
    const int lr  = lane & 7;
    const int hib = (lane >> 3) & 1;
    const int sec = lane >> 4;
    const uint32_t qk_base = smem_u32(sK) + ((sec * 8 + lr) * STR + hib * 4) * 4;
    const uint32_t pv_base = smem_u32(sV) + ((hib * 8 + lr) * STR + sec * 4) * 4;

    float o[8][4];
    #pragma unroll
    for (int n = 0; n < 8; n++)
        #pragma unroll
        for (int j = 0; j < 4; j++) o[n][j] = 0.f;
    float l0 = 0.f, l1 = 0.f;

    for (int c = 0; c < 6; c++) {
        const int kbase = q0 - 128 + c * 64;

        __syncthreads();
        // ---- Fill K and V (f16, zero OOB rows) ----
        #pragma unroll
        for (int i = 0; i < 4; i++) {
            int idx = tid + i * 256;
            int key = idx >> 4, c4 = idx & 15;
            int gk  = kbase + key;
            float4 kv = make_float4(0.f, 0.f, 0.f, 0.f), vv = kv;
            if ((unsigned)gk < (unsigned)T_FIX) {
                kv = Kg[(size_t)gk * 16 + c4];
                vv = Vg[(size_t)gk * 16 + c4];
            }
            sK[key * STR + c4 * 2]     = packh2(kv.x, kv.y);
            sK[key * STR + c4 * 2 + 1] = packh2(kv.z, kv.w);
            sV[key * STR + c4 * 2]     = packh2(vv.x, vv.y);
            sV[key * STR + c4 * 2 + 1] = packh2(vv.z, vv.w);
        }
        __syncthreads();

        // ---- 4 pairs of 16 keys each ----
        #pragma unroll
        for (int st = 0; st < 4; st++) {
            const int gp = c * 4 + st;
            if (gp < w || gp > w + 16) continue;    // warp-uniform band skip

            // -- QK: two 8-key tiles, 4 k-steps of 16 dims --
            float sA[4] = {0.f, 0.f, 0.f, 0.f};
            float sB[4] = {0.f, 0.f, 0.f, 0.f};
            const uint32_t qk_p = qk_base + (st * 16 * STR) * 4;
            #pragma unroll
            for (int s = 0; s < 4; s++) {
                uint32_t r0, r1, r2, r3;
                LDSM4(r0, r1, r2, r3, qk_p + s * 32);
                mma16(sA, qa[s], r0, r1);
                mma16(sB, qa[s], r2, r3);
            }

            // -- mask + exp2 (interior pairs skip all predicates) --
            float pA00, pA01, pA10, pA11, pB00, pB01, pB10, pB11;
            const int gk0 = kbase + st * 16 + 2 * cA;
            if (gp > w && gp < w + 16 &&
                kbase >= 0 && kbase + 64 <= T_FIX) {
                pA00 = ex2(sA[0]); pA01 = ex2(sA[1]);
                pA10 = ex2(sA[2]); pA11 = ex2(sA[3]);
                pB00 = ex2(sB[0]); pB01 = ex2(sB[1]);
                pB10 = ex2(sB[2]); pB11 = ex2(sB[3]);
            } else {
                const int cc = c * 64 + st * 16 + 2 * cA;
                bool iA0 = (unsigned)gk0       < (unsigned)T_FIX;
                bool iA1 = (unsigned)(gk0 + 1) < (unsigned)T_FIX;
                bool iB0 = (unsigned)(gk0 + 8) < (unsigned)T_FIX;
                bool iB1 = (unsigned)(gk0 + 9) < (unsigned)T_FIX;
                pA00 = (((unsigned)(cc     - rA)      < 256u) && iA0) ? ex2(sA[0]) : 0.f;
                pA01 = (((unsigned)(cc + 1 - rA)      < 256u) && iA1) ? ex2(sA[1]) : 0.f;
                pA10 = (((unsigned)(cc     - rA - 8)  < 256u) && iA0) ? ex2(sA[2]) : 0.f;
                pA11 = (((unsigned)(cc + 1 - rA - 8)  < 256u) && iA1) ? ex2(sA[3]) : 0.f;
                pB00 = (((unsigned)(cc + 8 - rA)      < 256u) && iB0) ? ex2(sB[0]) : 0.f;
                pB01 = (((unsigned)(cc + 9 - rA)      < 256u) && iB1) ? ex2(sB[1]) : 0.f;
                pB10 = (((unsigned)(cc + 8 - rA - 8)  < 256u) && iB0) ? ex2(sB[2]) : 0.f;
                pB11 = (((unsigned)(cc + 9 - rA - 8)  < 256u) && iB1) ? ex2(sB[3]) : 0.f;
            }
            l0 += (pA00 + pA01) + (pB00 + pB01);
            l1 += (pA10 + pA11) + (pB10 + pB11);

            // -- c-frag -> PV a-frag, in registers --
            uint32_t pa[4];
            pa[0] = packh2(pA00, pA01);
            pa[1] = packh2(pA10, pA11);
            pa[2] = packh2(pB00, pB01);
            pa[3] = packh2(pB10, pB11);

            // -- PV: one k16-step over these 16 keys, 8 dim-tiles --
            const uint32_t pv_p = pv_base + (st * 16 * STR) * 4;
            #pragma unroll
            for (int ndp = 0; ndp < 4; ndp++) {
                uint32_t v0, v1, v2, v3;
                LDSM4T(v0, v1, v2, v3, pv_p + ndp * 32);
                mma16(o[2 * ndp],     pa, v0, v1);
                mma16(o[2 * ndp + 1], pa, v2, v3);
            }
        }
    }

    // ---- normalize rows and store ----
    l0 += __shfl_xor_sync(0xffffffffu, l0, 1);
    l0 += __shfl_xor_sync(0xffffffffu, l0, 2);
    l1 += __shfl_xor_sync(0xffffffffu, l1, 1);
    l1 += __shfl_xor_sync(0xffffffffu, l1, 2);
    const float inv0 = __frcp_rn(l0);
    const float inv1 = __frcp_rn(l1);

    float* orow0 = Ob + (size_t)(q0 + rA) * 64;
    float* orow1 = Ob + (size_t)(q0 + rA + 8) * 64;
    #pragma unroll
    for (int nd = 0; nd < 8; nd++) {
        float2 u0 = make_float2(o[nd][0] * inv0, o[nd][1] * inv0);
        float2 u1 = make_float2(o[nd][2] * inv1, o[nd][3] * inv1);
        *(float2*)(orow0 + nd * 8 + 2 * cA) = u0;
        *(float2*)(orow1 + nd * 8 + 2 * cA) = u1;
    }
}

extern "C" void kernel_launch(void* const* d_in, const int* in_sizes, int n_in,
                              void* d_out, int out_size) {
    const float* Q = (const float*)d_in[0];
    const float* K = (const float*)d_in[1];
    const float* V = (const float*)d_in[2];
    float*       O = (float*)d_out;

    const int BH = in_sizes[0] / (T_FIX * 64);      // 24
    dim3 grid(BH * (T_FIX / MQ));                   // 768
    swa_f16_kernel<<<grid, 256>>>(Q, K, V, O);
}

// round 12
// speedup vs baseline: 1.2287x; 1.2287x over previous
#include <cuda_runtime.h>
#include <cuda_fp16.h>
#include <cstdint>

// Sliding-window attention B=2 H=12 T=4096 D=64 fp32, window [q-128, q+127].
// fp16 m16n8k16 mma.sync; ldmatrix K/V frags; P stays in registers.
// Round 12 = round 8 (best) + double-buffered K/V stages (fill of chunk c+1
// overlaps compute of chunk c; 7 barriers instead of 12) + chunk-level OOB
// skip (chunks are 64-aligned -> fully in or fully out; no T-bounds masks).

constexpr int T_FIX = 4096;
constexpr int MQ    = 128;
constexpr int STR   = 36;            // row stride in u32 units; conflict-free
constexpr int QF    = 128 * STR;     // Q staging: 4608 u32
constexpr int KVF   = 64 * STR;      // one tensor per stage: 2304 u32
constexpr int STAGE = 2 * KVF;       // K+V per stage: 4608 u32
constexpr int SM_BYTES = (QF + 2 * STAGE) * 4;   // 55296 B

__device__ __forceinline__ uint32_t smem_u32(const void* p) {
    uint32_t a;
    asm("{ .reg .u64 t; cvta.to.shared.u64 t, %1; cvt.u32.u64 %0, t; }" : "=r"(a) : "l"(p));
    return a;
}
__device__ __forceinline__ float ex2(float x) {
    float y; asm("ex2.approx.ftz.f32 %0, %1;" : "=f"(y) : "f"(x)); return y;
}
__device__ __forceinline__ uint32_t packh2(float lo, float hi) {
    __half2 h = __floats2half2_rn(lo, hi);
    return *(uint32_t*)&h;
}
__device__ __forceinline__ void mma16(float* c, const uint32_t* a,
                                      uint32_t b0, uint32_t b1) {
    asm volatile(
        "mma.sync.aligned.m16n8k16.row.col.f32.f16.f16.f32 "
        "{%0,%1,%2,%3}, {%4,%5,%6,%7}, {%8,%9}, {%0,%1,%2,%3};"
        : "+f"(c[0]), "+f"(c[1]), "+f"(c[2]), "+f"(c[3])
        : "r"(a[0]), "r"(a[1]), "r"(a[2]), "r"(a[3]), "r"(b0), "r"(b1));
}
#define LDSM4(r0,r1,r2,r3,addr) \
    asm volatile("ldmatrix.sync.aligned.m8n8.x4.shared.b16 {%0,%1,%2,%3}, [%4];" \
        : "=r"(r0),"=r"(r1),"=r"(r2),"=r"(r3) : "r"(addr))
#define LDSM4T(r0,r1,r2,r3,addr) \
    asm volatile("ldmatrix.sync.aligned.m8n8.x4.trans.shared.b16 {%0,%1,%2,%3}, [%4];" \
        : "=r"(r0),"=r"(r1),"=r"(r2),"=r"(r3) : "r"(addr))

__global__ __launch_bounds__(256, 2)
void swa_f16_kernel(const float* __restrict__ Q, const float* __restrict__ K,
                    const float* __restrict__ V, float* __restrict__ O)
{
    extern __shared__ uint32_t smem[];   // [Q | stage0 K,V | stage1 K,V]

    const int tid  = threadIdx.x;
    const int lane = tid & 31;
    const int w    = tid >> 5;

    const int ntiles = T_FIX / MQ;                  // 32
    const int bh = blockIdx.x / ntiles;
    const int q0 = (blockIdx.x % ntiles) * MQ;
    const size_t base = (size_t)bh * T_FIX * 64;
    const float4* Qg = (const float4*)(Q + base);
    const float4* Kg = (const float4*)(K + base);
    const float4* Vg = (const float4*)(V + base);
    float*        Ob = O + base;

    const float SC = 1.4426950408889634f * 0.125f;  // log2(e)/sqrt(64)

    // chunk c covers keys [q0-128+64c, q0-64+64c); 64-aligned -> all-in or all-out
    auto chunk_ok = [&](int c) {
        int kb = q0 - 128 + c * 64;
        return (unsigned)kb < (unsigned)T_FIX;
    };
    // fill stage (c&1) with chunk c's K/V (f16); chunk guaranteed in-bounds
    auto fill = [&](int c) {
        const int kbase = q0 - 128 + c * 64;
        uint32_t* kbuf = smem + QF + (c & 1) * STAGE;
        uint32_t* vbuf = kbuf + KVF;
        #pragma unroll
        for (int i = 0; i < 4; i++) {
            int idx = tid + i * 256;
            int key = idx >> 4, c4 = idx & 15;
            int gk  = kbase + key;
            float4 kv = Kg[(size_t)gk * 16 + c4];
            float4 vv = Vg[(size_t)gk * 16 + c4];
            kbuf[key * STR + c4 * 2]     = packh2(kv.x, kv.y);
            kbuf[key * STR + c4 * 2 + 1] = packh2(kv.z, kv.w);
            vbuf[key * STR + c4 * 2]     = packh2(vv.x, vv.y);
            vbuf[key * STR + c4 * 2 + 1] = packh2(vv.z, vv.w);
        }
    };

    // ---- Prologue: stage Q (scaled, f16) + fill chunk 0 ----
    #pragma unroll
    for (int i = 0; i < 8; i++) {
        int idx = tid + i * 256;
        int row = idx >> 4, c4 = idx & 15;
        float4 v = Qg[(size_t)(q0 + row) * 16 + c4];
        smem[row * STR + c4 * 2]     = packh2(v.x * SC, v.y * SC);
        smem[row * STR + c4 * 2 + 1] = packh2(v.z * SC, v.w * SC);
    }
    if (chunk_ok(0)) fill(0);
    __syncthreads();

    // ---- Q a-fragments (m16n8k16): qa[s] covers dims 16s..16s+15 ----
    const int rA = w * 16 + (lane >> 2);
    const int cA = lane & 3;
    uint32_t qa[4][4];
    #pragma unroll
    for (int s = 0; s < 4; s++) {
        qa[s][0] = smem[rA * STR + s * 8 + cA];
        qa[s][1] = smem[(rA + 8) * STR + s * 8 + cA];
        qa[s][2] = smem[rA * STR + s * 8 + 4 + cA];
        qa[s][3] = smem[(rA + 8) * STR + s * 8 + 4 + cA];
    }

    // ---- ldmatrix per-lane offsets (bytes, within a stage) ----
    const int lr  = lane & 7;
    const int hib = (lane >> 3) & 1;
    const int sec = lane >> 4;
    const uint32_t sb = smem_u32(smem);
    const uint32_t qk_lane = ((sec * 8 + lr) * STR + hib * 4) * 4;
    const uint32_t pv_lane = ((hib * 8 + lr) * STR + sec * 4) * 4 + KVF * 4;

    float o[8][4];
    #pragma unroll
    for (int n = 0; n < 8; n++)
        #pragma unroll
        for (int j = 0; j < 4; j++) o[n][j] = 0.f;
    float l0 = 0.f, l1 = 0.f;

    for (int c = 0; c < 6; c++) {
        if (chunk_ok(c)) {
            const uint32_t stb = sb + (QF + (c & 1) * STAGE) * 4;

            // ---- 4 pairs of 16 keys each ----
            #pragma unroll
            for (int st = 0; st < 4; st++) {
                const int gp = c * 4 + st;
                if (gp < w || gp > w + 16) continue;    // warp-uniform band skip

                // -- QK: two 8-key tiles, 4 k-steps of 16 dims --
                float sA[4] = {0.f, 0.f, 0.f, 0.f};
                float sB[4] = {0.f, 0.f, 0.f, 0.f};
                const uint32_t qk_p = stb + qk_lane + (st * 16 * STR) * 4;
                #pragma unroll
                for (int s = 0; s < 4; s++) {
                    uint32_t r0, r1, r2, r3;
                    LDSM4(r0, r1, r2, r3, qk_p + s * 32);
                    mma16(sA, qa[s], r0, r1);
                    mma16(sB, qa[s], r2, r3);
                }

                // -- softmax: interior fast path; edge pairs use window mask only --
                float pA00, pA01, pA10, pA11, pB00, pB01, pB10, pB11;
                if (gp > w && gp < w + 16) {
                    pA00 = ex2(sA[0]); pA01 = ex2(sA[1]);
                    pA10 = ex2(sA[2]); pA11 = ex2(sA[3]);
                    pB00 = ex2(sB[0]); pB01 = ex2(sB[1]);
                    pB10 = ex2(sB[2]); pB11 = ex2(sB[3]);
                } else {
                    const int cc = c * 64 + st * 16 + 2 * cA;   // local col of sA c0
                    pA00 = ((unsigned)(cc     - rA)      < 256u) ? ex2(sA[0]) : 0.f;
                    pA01 = ((unsigned)(cc + 1 - rA)      < 256u) ? ex2(sA[1]) : 0.f;
                    pA10 = ((unsigned)(cc     - rA - 8)  < 256u) ? ex2(sA[2]) : 0.f;
                    pA11 = ((unsigned)(cc + 1 - rA - 8)  < 256u) ? ex2(sA[3]) : 0.f;
                    pB00 = ((unsigned)(cc + 8 - rA)      < 256u) ? ex2(sB[0]) : 0.f;
                    pB01 = ((unsigned)(cc + 9 - rA)      < 256u) ? ex2(sB[1]) : 0.f;
                    pB10 = ((unsigned)(cc + 8 - rA - 8)  < 256u) ? ex2(sB[2]) : 0.f;
                    pB11 = ((unsigned)(cc + 9 - rA - 8)  < 256u) ? ex2(sB[3]) : 0.f;
                }
                l0 += (pA00 + pA01) + (pB00 + pB01);
                l1 += (pA10 + pA11) + (pB10 + pB11);

                // -- c-frag -> PV a-frag, in registers --
                uint32_t pa[4];
                pa[0] = packh2(pA00, pA01);
                pa[1] = packh2(pA10, pA11);
                pa[2] = packh2(pB00, pB01);
                pa[3] = packh2(pB10, pB11);

                // -- PV: one k16-step over these 16 keys, 8 dim-tiles --
                const uint32_t pv_p = stb + pv_lane + (st * 16 * STR) * 4;
                #pragma unroll
                for (int ndp = 0; ndp < 4; ndp++) {
                    uint32_t v0, v1, v2, v3;
                    LDSM4T(v0, v1, v2, v3, pv_p + ndp * 32);
                    mma16(o[2 * ndp],     pa, v0, v1);
                    mma16(o[2 * ndp + 1], pa, v2, v3);
                }
            }
        }

        // ---- fill next chunk into the other stage (overlaps other warps'
        //      compute; stage of chunk c is reused only after the barrier) ----
        if (c < 5 && chunk_ok(c + 1)) fill(c + 1);
        __syncthreads();
    }

    // ---- normalize rows and store ----
    l0 += __shfl_xor_sync(0xffffffffu, l0, 1);
    l0 += __shfl_xor_sync(0xffffffffu, l0, 2);
    l1 += __shfl_xor_sync(0xffffffffu, l1, 1);
    l1 += __shfl_xor_sync(0xffffffffu, l1, 2);
    const float inv0 = __frcp_rn(l0);
    const float inv1 = __frcp_rn(l1);

    float* orow0 = Ob + (size_t)(q0 + rA) * 64;
    float* orow1 = Ob + (size_t)(q0 + rA + 8) * 64;
    #pragma unroll
    for (int nd = 0; nd < 8; nd++) {
        float2 u0 = make_float2(o[nd][0] * inv0, o[nd][1] * inv0);
        float2 u1 = make_float2(o[nd][2] * inv1, o[nd][3] * inv1);
        *(float2*)(orow0 + nd * 8 + 2 * cA) = u0;
        *(float2*)(orow1 + nd * 8 + 2 * cA) = u1;
    }
}

extern "C" void kernel_launch(void* const* d_in, const int* in_sizes, int n_in,
                              void* d_out, int out_size) {
    const float* Q = (const float*)d_in[0];
    const float* K = (const float*)d_in[1];
    const float* V = (const float*)d_in[2];
    float*       O = (float*)d_out;

    const int BH = in_sizes[0] / (T_FIX * 64);      // 24
    static bool attr_set = false;
    if (!attr_set) {
        cudaFuncSetAttribute(swa_f16_kernel,
                             cudaFuncAttributeMaxDynamicSharedMemorySize, SM_BYTES);
        attr_set = true;
    }
    dim3 grid(BH * (T_FIX / MQ));                   // 768
    swa_f16_kernel<<<grid, 256, SM_BYTES>>>(Q, K, V, O);
}